// round 13
// baseline (speedup 1.0000x reference)
#include <cuda_runtime.h>
#include <math.h>

#define N_NODES 50000
#define B 64
#define M 32
#define E 128
#define H 8

// scratch (allocation-free rule: __device__ globals)
__device__ float g_zsum[B * E];
__device__ float g_cnt[B];
__device__ float g_wv[B * E];        // tanh(write_values)
__device__ float g_att2[B * M * H];
__device__ float g_mvwo[B * M * E];  // mv @ Wo

// ---------------------------------------------------------------------------
// kzero: clear accumulators
// ---------------------------------------------------------------------------
__global__ void kzero() {
    int i = blockIdx.x * 256 + threadIdx.x;
    if (i < B * E) g_zsum[i] = 0.f;
    if (i < B) g_cnt[i] = 0.f;
}

// ---------------------------------------------------------------------------
// kS: zsum[g] = segment_sum(z), cnt[g] = node count. 256 nodes/block.
// ---------------------------------------------------------------------------
__global__ void kS(const float* __restrict__ z, const int* __restrict__ batch) {
    __shared__ int bats[256];
    const int tid = threadIdx.x;
    const int nb0 = blockIdx.x * 256;
    const int nvalid = min(256, N_NODES - nb0);
    bats[tid] = (tid < nvalid) ? batch[nb0 + tid] : -1;
    __syncthreads();

    const int c = tid & 127;
    const int base = (tid >> 7) * 128;
    float run = 0.f, runc = 0.f;
    int curg = -1;
#pragma unroll 4
    for (int j = 0; j < 128; j++) {
        int node = base + j;
        int g = bats[node];
        if (g != curg) {
            if (curg >= 0) {
                atomicAdd(&g_zsum[curg * E + c], run);
                if (c == 0) atomicAdd(&g_cnt[curg], runc);
            }
            curg = g; run = 0.f; runc = 0.f;
        }
        if (g >= 0) {
            run += z[(size_t)(nb0 + node) * E + c];
            runc += 1.f;
        }
    }
    if (curg >= 0) {
        atomicAdd(&g_zsum[curg * E + c], run);
        if (c == 0) atomicAdd(&g_cnt[curg], runc);
    }
}

// ---------------------------------------------------------------------------
// kP: one block per graph b: mvWo, att2, tanh(write_values)
// ---------------------------------------------------------------------------
__global__ void __launch_bounds__(256, 1)
kP(const float* __restrict__ mv, const float* __restrict__ Wo,
   const float* __restrict__ Wa2, const float* __restrict__ ba2,
   const float* __restrict__ Wv, const float* __restrict__ bv) {
    extern __shared__ float sp[];
    float* Wos = sp;            // [128][128]
    float* mvs = sp + E * E;    // [32][128]
    const int b = blockIdx.x, tid = threadIdx.x;

    for (int i = tid; i < E * E / 4; i += 256)
        ((float4*)Wos)[i] = ((const float4*)Wo)[i];
    for (int i = tid; i < M * E / 4; i += 256)
        ((float4*)mvs)[i] = ((const float4*)(mv + (size_t)b * M * E))[i];
    __syncthreads();

    // mvWo: thread tile 4 m-rows x 4 cols
    {
        const int cg = tid & 31;
        const int mb = (tid >> 5) * 4;
        float acc[4][4];
#pragma unroll
        for (int j = 0; j < 4; j++)
            acc[j][0] = acc[j][1] = acc[j][2] = acc[j][3] = 0.f;
        for (int kq = 0; kq < 32; kq++) {
            const float4* wrow = (const float4*)(Wos + kq * 4 * E) + cg;
            float4 w0 = wrow[0], w1 = wrow[32], w2 = wrow[64], w3 = wrow[96];
#pragma unroll
            for (int j = 0; j < 4; j++) {
                float4 zv = ((const float4*)(mvs + (mb + j) * E))[kq];
                acc[j][0] += zv.x * w0.x + zv.y * w1.x + zv.z * w2.x + zv.w * w3.x;
                acc[j][1] += zv.x * w0.y + zv.y * w1.y + zv.z * w2.y + zv.w * w3.y;
                acc[j][2] += zv.x * w0.z + zv.y * w1.z + zv.z * w2.z + zv.w * w3.z;
                acc[j][3] += zv.x * w0.w + zv.y * w1.w + zv.z * w2.w + zv.w * w3.w;
            }
        }
#pragma unroll
        for (int j = 0; j < 4; j++)
            ((float4*)(g_mvwo + (size_t)b * M * E + (mb + j) * E))[cg] =
                make_float4(acc[j][0], acc[j][1], acc[j][2], acc[j][3]);
    }

    // att2: thread = (m, h)
    {
        const int m = tid >> 3, h = tid & 7;
        const float* row = mvs + m * E;
        float s = 0.f;
#pragma unroll 8
        for (int e = 0; e < E; e++) s += row[e] * Wa2[e * H + h];
        g_att2[(b * M + m) * H + h] = s + ba2[h];
    }

    // write_values: threads 0..127, col c
    if (tid < E) {
        float s = g_cnt[b] * bv[tid];
        const float* zs = g_zsum + b * E;
#pragma unroll 8
        for (int k = 0; k < E; k++) s += zs[k] * Wv[k * E + tid];
        g_wv[b * E + tid] = tanhf(s);
    }
}

// ---------------------------------------------------------------------------
// kATT: one warp per 8 consecutive nodes (same graph ~99% of warps).
//   phase 1: coefs c[8] per lane (lane = slot), warp-sequential per node
//   phase 2: einsum — uniform-g fast path streams mvWo[g] ONCE for 8 nodes
// ---------------------------------------------------------------------------
__global__ void __launch_bounds__(256)
kATT(const float* __restrict__ z, const int* __restrict__ batch,
     const float* __restrict__ bias_mask,
     const float* __restrict__ Wa1, const float* __restrict__ ba1,
     const float* __restrict__ Wh, const float* __restrict__ bh,
     const float* __restrict__ bo, float* __restrict__ out) {
    __shared__ float wa1t[H * E];   // [h][k]
    const int tid = threadIdx.x;
    for (int i = tid; i < E * H; i += 256) {
        int h = i >> 7, k = i & 127;
        wa1t[h * E + k] = Wa1[k * H + h];
    }
    __syncthreads();

    const int lane = tid & 31;
    const int nbase = blockIdx.x * 64 + (tid >> 5) * 8;   // 8 nodes / warp
    const float bh0 = bh[0];
    const float whv = (lane < H) ? Wh[lane] : 0.f;

    // graph ids for the 8 nodes (batch sorted -> uni iff endpoints match)
    int gj[8];
#pragma unroll
    for (int j = 0; j < 8; j++) {
        int n = nbase + j;
        gj[j] = (n < N_NODES) ? batch[n] : -1;
    }
    const bool uni = (gj[0] == gj[7]);   // implies all 8 equal (sorted)

    // hoistable per-g data (reloaded per node on boundary warps)
    float a2v[8];
    float biasm = 0.f;
    if (uni) {
        const float4* a2p = (const float4*)(g_att2 + ((size_t)gj[0] * M + lane) * H);
        float4 x = a2p[0], y = a2p[1];
        a2v[0] = x.x; a2v[1] = x.y; a2v[2] = x.z; a2v[3] = x.w;
        a2v[4] = y.x; a2v[5] = y.y; a2v[6] = y.z; a2v[7] = y.w;
        biasm = (bias_mask[gj[0] * M + lane] - 1.f) * 1e9f;
    }

    // --- phase 1: coefs for 8 nodes ---
    float cj[8];
#pragma unroll
    for (int j = 0; j < 8; j++) {
        int n = nbase + j;
        int g = (gj[j] >= 0) ? gj[j] : 0;
        if (!uni) {
            const float4* a2p = (const float4*)(g_att2 + ((size_t)g * M + lane) * H);
            float4 x = a2p[0], y = a2p[1];
            a2v[0] = x.x; a2v[1] = x.y; a2v[2] = x.z; a2v[3] = x.w;
            a2v[4] = y.x; a2v[5] = y.y; a2v[6] = y.z; a2v[7] = y.w;
            biasm = (bias_mask[g * M + lane] - 1.f) * 1e9f;
        }
        float4 z4 = (n < N_NODES)
            ? ((const float4*)(z + (size_t)n * E))[lane]
            : make_float4(0.f, 0.f, 0.f, 0.f);

        float w = bh0;
#pragma unroll
        for (int h = 0; h < H; h++) {
            // att1[h] = z[n] @ Wa1[:,h] + ba1[h] (butterfly)
            float4 w4 = ((const float4*)(wa1t + h * E))[lane];
            float p = z4.x * w4.x + z4.y * w4.y + z4.z * w4.z + z4.w * w4.w;
#pragma unroll
            for (int off = 16; off > 0; off >>= 1)
                p += __shfl_xor_sync(0xffffffffu, p, off);
            float l = p + ba1[h] + a2v[h];
            l = (l >= 0.f) ? l : 0.01f * l;   // leaky_relu
            l += biasm;
            float mx = l;
#pragma unroll
            for (int off = 16; off > 0; off >>= 1)
                mx = fmaxf(mx, __shfl_xor_sync(0xffffffffu, mx, off));
            float e = __expf(l - mx);
            float s = e;
#pragma unroll
            for (int off = 16; off > 0; off >>= 1)
                s += __shfl_xor_sync(0xffffffffu, s, off);
            w += (e / s) * __shfl_sync(0xffffffffu, whv, h);
        }
        // second softmax over slots (lanes)
        float mx2 = w;
#pragma unroll
        for (int off = 16; off > 0; off >>= 1)
            mx2 = fmaxf(mx2, __shfl_xor_sync(0xffffffffu, mx2, off));
        float e2 = __expf(w - mx2);
        float s2 = e2;
#pragma unroll
        for (int off = 16; off > 0; off >>= 1)
            s2 += __shfl_xor_sync(0xffffffffu, s2, off);
        cj[j] = e2 / s2;
    }

    // --- phase 2: einsum + bias + store ---
    float4 bo4 = ((const float4*)bo)[lane];
    if (uni && gj[0] >= 0) {
        // fast path: stream mvWo[g] once for all 8 nodes
        const float4* mw = (const float4*)(g_mvwo + (size_t)gj[0] * M * E);
        float4 acc[8];
#pragma unroll
        for (int j = 0; j < 8; j++) acc[j] = bo4;
#pragma unroll 4
        for (int m = 0; m < M; m++) {
            float4 v = mw[m * 32 + lane];
#pragma unroll
            for (int j = 0; j < 8; j++) {
                float cm = __shfl_sync(0xffffffffu, cj[j], m);
                acc[j].x += cm * v.x; acc[j].y += cm * v.y;
                acc[j].z += cm * v.z; acc[j].w += cm * v.w;
            }
        }
#pragma unroll
        for (int j = 0; j < 8; j++)
            ((float4*)(out + (size_t)(nbase + j) * E))[lane] = acc[j];
    } else {
        // boundary warp: per-node path
#pragma unroll
        for (int j = 0; j < 8; j++) {
            int n = nbase + j;
            if (n >= N_NODES) break;
            const float4* mw = (const float4*)(g_mvwo + (size_t)gj[j] * M * E);
            float4 acc = bo4;
#pragma unroll 8
            for (int m = 0; m < M; m++) {
                float cm = __shfl_sync(0xffffffffu, cj[j], m);
                float4 v = mw[m * 32 + lane];
                acc.x += cm * v.x; acc.y += cm * v.y;
                acc.z += cm * v.z; acc.w += cm * v.w;
            }
            ((float4*)(out + (size_t)n * E))[lane] = acc;
        }
    }
}

// ---------------------------------------------------------------------------
// k2: state updates + arange
// out layout: [output N*E | arange N | new_mv B*M*E | new_write_mask | new_bias_mask]
// ---------------------------------------------------------------------------
__global__ void k2_final(const float* __restrict__ mv,
                         const float* __restrict__ write_mask,
                         const float* __restrict__ bias_mask,
                         float* __restrict__ out) {
    int idx = blockIdx.x * blockDim.x + threadIdx.x;
    const size_t OUT1 = (size_t)N_NODES * E;
    const size_t OUT2 = OUT1 + N_NODES;
    const size_t OUT3 = OUT2 + (size_t)B * M * E;
    const size_t OUT4 = OUT3 + (size_t)B * M;
    if (idx < B * M * E) {
        int b = idx >> 12;
        int m = (idx >> 7) & 31;
        out[OUT2 + idx] = mv[idx] + g_wv[b * E + (idx & 127)] * write_mask[b * M + m];
    }
    if (idx < B * M) {
        int b = idx >> 5, m = idx & 31;
        out[OUT3 + idx] = write_mask[b * M + ((m + 31) & 31)];        // roll(+1)
        out[OUT4 + idx] = fminf(bias_mask[idx] + write_mask[idx], 1.f);
    }
    if (idx < N_NODES) out[OUT1 + idx] = (float)idx;                  // arange
}

// ---------------------------------------------------------------------------
extern "C" void kernel_launch(void* const* d_in, const int* in_sizes, int n_in,
                              void* d_out, int out_size) {
    const float* z     = (const float*)d_in[0];
    const int*   batch = (const int*)d_in[1];
    const float* mv    = (const float*)d_in[2];
    const float* wm    = (const float*)d_in[3];
    const float* bm    = (const float*)d_in[4];
    const float* Wv    = (const float*)d_in[5];
    const float* bv    = (const float*)d_in[6];
    const float* Wo    = (const float*)d_in[7];
    const float* bo    = (const float*)d_in[8];
    const float* Wa1   = (const float*)d_in[9];
    const float* ba1   = (const float*)d_in[10];
    const float* Wa2   = (const float*)d_in[11];
    const float* ba2   = (const float*)d_in[12];
    const float* Wh    = (const float*)d_in[13];
    const float* bh    = (const float*)d_in[14];
    float* out = (float*)d_out;

    const int SMEM_P = (E * E + M * E) * 4;   // 80 KB
    cudaFuncSetAttribute(kP, cudaFuncAttributeMaxDynamicSharedMemorySize, SMEM_P);

    kzero<<<32, 256>>>();
    kS<<<(N_NODES + 255) / 256, 256>>>(z, batch);
    kP<<<B, 256, SMEM_P>>>(mv, Wo, Wa2, ba2, Wv, bv);
    kATT<<<(N_NODES + 63) / 64, 256>>>(z, batch, bm, Wa1, ba1, Wh, bh, bo, out);
    k2_final<<<(B * M * E + 255) / 256, 256>>>(mv, wm, bm, out);
}